// round 9
// baseline (speedup 1.0000x reference)
#include <cuda_runtime.h>
#include <cuda_bf16.h>
#include <cstdint>

// Segment-wise mean(|diff|): x flattened is [num_segs, L] contiguous.
// out[g] = mean_{i=0..L-2} |x[g*L+i+1] - x[g*L+i]|
//
// Fast path: one warp per segment; loads via cp.async.bulk (UBLKCP) into a
// 3-stage x 2KB per-warp smem ring with per-warp mbarriers. In-flight bytes
// are smem-bounded (~128KB/SM), not register-bounded, so DRAM latency is
// fully covered. Compute: conflict-free LDS.128 (lane-contiguous 16B),
// rotating-shuffle junctions, stage-boundary gap carried in a register.

#define NSTAGE        3
#define STAGE_FLOATS  512
#define STAGE_BYTES   2048
#define WARPS_PER_CTA 8
#define SMEM_DATA_OFF 1024
#define SMEM_TOTAL    (SMEM_DATA_OFF + WARPS_PER_CTA * NSTAGE * STAGE_BYTES)

__global__ __launch_bounds__(256) void seg_bulk_kernel(
    const float* __restrict__ x,
    float* __restrict__ out,
    int L,        // floats per segment, multiple of 512
    int nst,      // L / 512
    float inv,    // 1/(L-1)
    int num_segs)
{
    extern __shared__ unsigned char smem[];
    const int wid  = threadIdx.x >> 5;
    const int lane = threadIdx.x & 31;
    const int gwarp = blockIdx.x * WARPS_PER_CTA + wid;
    if (gwarp >= num_segs) return;

    // Per-warp private smem: mbarriers + stage ring.
    const uint32_t smem_base = (uint32_t)__cvta_generic_to_shared(smem);
    const uint32_t bar0  = smem_base + wid * (NSTAGE * 8);
    unsigned char* data  = smem + SMEM_DATA_OFF + wid * (NSTAGE * STAGE_BYTES);
    const uint32_t data0 = smem_base + SMEM_DATA_OFF + wid * (NSTAGE * STAGE_BYTES);

    if (lane == 0) {
        #pragma unroll
        for (int s = 0; s < NSTAGE; s++)
            asm volatile("mbarrier.init.shared.b64 [%0], 1;"
                         :: "r"(bar0 + s * 8) : "memory");
        asm volatile("fence.proxy.async.shared::cta;" ::: "memory");
    }
    __syncwarp();

    const float* gseg = x + (long long)gwarp * L;

    // Prologue: fill the ring.
    if (lane == 0) {
        #pragma unroll
        for (int s = 0; s < NSTAGE; s++) {
            if (s < nst) {
                asm volatile("mbarrier.arrive.expect_tx.shared.b64 _, [%0], %1;"
                             :: "r"(bar0 + s * 8), "r"(STAGE_BYTES) : "memory");
                asm volatile(
                    "cp.async.bulk.shared::cluster.global.mbarrier::complete_tx::bytes "
                    "[%0], [%1], %2, [%3];"
                    :: "r"(data0 + s * STAGE_BYTES),
                       "l"(gseg + (long long)s * STAGE_FLOATS),
                       "r"(STAGE_BYTES), "r"(bar0 + s * 8) : "memory");
            }
        }
    }

    float sum = 0.0f;
    float prev_last = 0.0f;  // last element of previous stage (broadcast)

    for (int b = 0; b < nst; b++) {
        const int slot = b % NSTAGE;
        const uint32_t phase = (uint32_t)((b / NSTAGE) & 1u);
        const uint32_t mbar = bar0 + slot * 8;

        // Wait for stage b.
        {
            uint32_t done;
            asm volatile("{\n\t.reg .pred p;\n\t"
                         "mbarrier.try_wait.parity.acquire.cta.shared::cta.b64 p, [%1], %2;\n\t"
                         "selp.b32 %0, 1, 0, p;\n\t}"
                         : "=r"(done) : "r"(mbar), "r"(phase) : "memory");
            while (!done) {
                asm volatile("{\n\t.reg .pred p;\n\t"
                             "mbarrier.try_wait.parity.acquire.cta.shared::cta.b64 p, [%1], %2, 0x989680;\n\t"
                             "selp.b32 %0, 1, 0, p;\n\t}"
                             : "=r"(done) : "r"(mbar), "r"(phase) : "memory");
            }
        }

        // Load 4 chunks: chunk c, lane l -> floats [c*128 + l*4, +4).
        // Lane-contiguous 16B => conflict-free LDS.128.
        float4 ch[4];
        const float4* sp = reinterpret_cast<const float4*>(data + slot * STAGE_BYTES);
        #pragma unroll
        for (int c = 0; c < 4; c++)
            ch[c] = sp[c * 32 + lane];

        __syncwarp();  // all lanes done reading this slot

        // Reissue slot for stage b+NSTAGE (overlaps with compute below).
        if (lane == 0 && b + NSTAGE < nst) {
            asm volatile("fence.proxy.async.shared::cta;" ::: "memory");
            asm volatile("mbarrier.arrive.expect_tx.shared.b64 _, [%0], %1;"
                         :: "r"(mbar), "r"(STAGE_BYTES) : "memory");
            asm volatile(
                "cp.async.bulk.shared::cluster.global.mbarrier::complete_tx::bytes "
                "[%0], [%1], %2, [%3];"
                :: "r"(data0 + slot * STAGE_BYTES),
                   "l"(gseg + (long long)(b + NSTAGE) * STAGE_FLOATS),
                   "r"(STAGE_BYTES), "r"(mbar) : "memory");
        }

        // Stage-boundary gap (deferred from previous stage), added on lane 0.
        const float first = __shfl_sync(0xFFFFFFFFu, ch[0].x, 0);
        if (b > 0 && lane == 0) sum += fabsf(first - prev_last);

        // Intra-stage gaps. Rotating shuffle per chunk:
        // lane l<31 gets lane l+1's ch[c].x; lane 31 gets chunk c+1's first
        // element (lane 0 sources ch[c+1].x). For c==3 lane31's gap is the
        // (deferred) stage boundary -> skip here.
        #pragma unroll
        for (int c = 0; c < 4; c++) {
            const float src = (lane == 0 && c < 3) ? ch[c + 1].x : ch[c].x;
            float nx = __shfl_sync(0xFFFFFFFFu, src, (lane + 1) & 31);
            if (c == 3 && lane == 31) nx = ch[3].w;  // zero contribution
            sum += fabsf(ch[c].y - ch[c].x) + fabsf(ch[c].z - ch[c].y)
                 + fabsf(ch[c].w - ch[c].z) + fabsf(nx - ch[c].w);
        }
        prev_last = __shfl_sync(0xFFFFFFFFu, ch[3].w, 31);
    }

    // Warp reduction, lane 0 writes the segment mean.
    #pragma unroll
    for (int off = 16; off > 0; off >>= 1)
        sum += __shfl_down_sync(0xFFFFFFFFu, sum, off);
    if (lane == 0)
        out[gwarp] = sum * inv;
}

// Mid path: warp per segment, float4 register pipeline (L multiple of 128).
__global__ __launch_bounds__(256) void seg_warp_kernel(
    const float* __restrict__ x,
    float* __restrict__ out,
    int n4, int nchunks, float inv, int num_segs)
{
    const int gwarp = (blockIdx.x * 256 + threadIdx.x) >> 5;
    const int lane  = threadIdx.x & 31;
    if (gwarp >= num_segs) return;

    const float4* __restrict__ p4 =
        reinterpret_cast<const float4*>(x) + (long long)gwarp * n4;

    float sum = 0.0f;
    float4 v = __ldg(p4 + lane);

    #pragma unroll 4
    for (int c = 1; c < nchunks; c++) {
        float4 nv = __ldg(p4 + c * 32 + lane);
        float src = (lane == 0) ? nv.x : v.x;
        float nx  = __shfl_sync(0xFFFFFFFFu, src, (lane + 1) & 31);
        sum += fabsf(v.y - v.x) + fabsf(v.z - v.y)
             + fabsf(v.w - v.z) + fabsf(nx  - v.w);
        v = nv;
    }
    {
        float nx = __shfl_sync(0xFFFFFFFFu, v.x, (lane + 1) & 31);
        if (lane == 31) nx = v.w;
        sum += fabsf(v.y - v.x) + fabsf(v.z - v.y)
             + fabsf(v.w - v.z) + fabsf(nx  - v.w);
    }

    #pragma unroll
    for (int off = 16; off > 0; off >>= 1)
        sum += __shfl_down_sync(0xFFFFFFFFu, sum, off);
    if (lane == 0)
        out[gwarp] = sum * inv;
}

// Generic fallback: one CTA per segment, scalar loads (any L >= 2).
__global__ __launch_bounds__(256) void seg_generic_kernel(
    const float* __restrict__ x,
    float* __restrict__ out,
    int L, float inv)
{
    const long long seg = blockIdx.x;
    const float* __restrict__ p = x + seg * (long long)L;
    const int tid = threadIdx.x;

    float sum = 0.0f;
    for (int i = tid; i < L - 1; i += blockDim.x)
        sum += fabsf(__ldg(p + i + 1) - __ldg(p + i));

    #pragma unroll
    for (int off = 16; off > 0; off >>= 1)
        sum += __shfl_down_sync(0xFFFFFFFFu, sum, off);

    __shared__ float wsum[8];
    const int lane = tid & 31, wid = tid >> 5;
    if (lane == 0) wsum[wid] = sum;
    __syncthreads();
    if (wid == 0) {
        float s = (lane < 8) ? wsum[lane] : 0.0f;
        #pragma unroll
        for (int off = 4; off > 0; off >>= 1)
            s += __shfl_down_sync(0xFFFFFFFFu, s, off);
        if (lane == 0) out[seg] = s * inv;
    }
}

extern "C" void kernel_launch(void* const* d_in, const int* in_sizes, int n_in,
                              void* d_out, int out_size)
{
    const float* x = (const float*)d_in[0];
    float* out = (float*)d_out;

    const long long total = (long long)in_sizes[0];
    const int num_segs = out_size;                     // B * target_len
    const int L = (int)(total / (long long)num_segs);  // segment length
    const float inv = 1.0f / (float)(L - 1);

    if ((L % STAGE_FLOATS) == 0) {
        const int nst = L / STAGE_FLOATS;
        const int ctas = (num_segs + WARPS_PER_CTA - 1) / WARPS_PER_CTA;
        cudaFuncSetAttribute(seg_bulk_kernel,
                             cudaFuncAttributeMaxDynamicSharedMemorySize,
                             SMEM_TOTAL);
        seg_bulk_kernel<<<ctas, 256, SMEM_TOTAL>>>(x, out, L, nst, inv, num_segs);
    } else if ((L & 127) == 0) {
        const int n4 = L >> 2;
        const int ctas = (num_segs * 32 + 255) / 256;
        seg_warp_kernel<<<ctas, 256>>>(x, out, n4, n4 >> 5, inv, num_segs);
    } else {
        seg_generic_kernel<<<num_segs, 256>>>(x, out, L, inv);
    }
}

// round 10
// speedup vs baseline: 1.4944x; 1.4944x over previous
#include <cuda_runtime.h>
#include <cuda_bf16.h>

// Segment-wise mean(|diff|): x flattened is [num_segs, L] contiguous.
// out[g] = mean_{i=0..L-2} |x[g*L+i+1] - x[g*L+i]|
//
// Fast path: one warp per segment, double-buffered load pipeline (BATCH=4
// chunks of 32 float4 = 2 KB per batch) + an L2 prefetch prologue that pulls
// the segment's remaining lines into L2 register-free, so demand loads for
// batches 1..N see L2-hit latency; demand loads use .cs (evict-first) so the
// streamed lines don't displace prefetched ones. This exact combination is
// the empirical best (R5: 37.6us timed). Cross-vector junctions via one
// rotating shuffle per chunk. No smem, no __syncthreads.

#define BATCH 4

__global__ __launch_bounds__(256) void seg_warp_pipe_kernel(
    const float* __restrict__ x,
    float* __restrict__ out,
    int n4,         // float4s per segment (L/4), multiple of 128
    int nbatches,   // n4 / (32*BATCH), >= 2
    float inv,      // 1/(L-1)
    int num_segs)
{
    const int gwarp = (blockIdx.x * 256 + threadIdx.x) >> 5;
    const int lane  = threadIdx.x & 31;
    if (gwarp >= num_segs) return;

    const float4* __restrict__ pseg =
        reinterpret_cast<const float4*>(x) + (long long)gwarp * n4;
    const float4* __restrict__ p4 = pseg + lane;

    // L2 prefetch prologue: pull lines for batches 1..nbatches-1 into L2.
    // Segment has n4/8 128-byte lines; batch 0 (first 16 lines) is demand-
    // loaded immediately below, so start at line 16. Register-free MLP.
    {
        const char* base = reinterpret_cast<const char*>(pseg);
        const int nlines = n4 >> 3;
        for (int ln = 16 + lane; ln < nlines; ln += 32) {
            asm volatile("prefetch.global.L2 [%0];" :: "l"(base + (long long)ln * 128));
        }
    }

    float4 buf[BATCH];
    #pragma unroll
    for (int i = 0; i < BATCH; i++)
        buf[i] = __ldcs(p4 + i * 32);

    float sum = 0.0f;

    for (int b = 1; b < nbatches; b++) {
        // Issue next batch's loads first (independent of current compute).
        float4 nbuf[BATCH];
        const float4* q = p4 + b * (BATCH * 32);
        #pragma unroll
        for (int i = 0; i < BATCH; i++)
            nbuf[i] = __ldcs(q + i * 32);

        // Compute current batch.
        #pragma unroll
        for (int i = 0; i < BATCH; i++) {
            const float nextx = (i < BATCH - 1) ? buf[i + 1].x : nbuf[0].x;
            const float src = (lane == 0) ? nextx : buf[i].x;
            const float nx  = __shfl_sync(0xFFFFFFFFu, src, (lane + 1) & 31);
            sum += fabsf(buf[i].y - buf[i].x) + fabsf(buf[i].z - buf[i].y)
                 + fabsf(buf[i].w - buf[i].z) + fabsf(nx - buf[i].w);
        }

        #pragma unroll
        for (int i = 0; i < BATCH; i++) buf[i] = nbuf[i];
    }

    // Final batch: last chunk's lane 31 has no successor (segment end).
    #pragma unroll
    for (int i = 0; i < BATCH; i++) {
        const float nextx = (i < BATCH - 1) ? buf[i + 1].x : buf[i].x;
        const float src = (lane == 0) ? nextx : buf[i].x;
        float nx = __shfl_sync(0xFFFFFFFFu, src, (lane + 1) & 31);
        if (i == BATCH - 1 && lane == 31) nx = buf[i].w;  // zero contribution
        sum += fabsf(buf[i].y - buf[i].x) + fabsf(buf[i].z - buf[i].y)
             + fabsf(buf[i].w - buf[i].z) + fabsf(nx - buf[i].w);
    }

    // Warp reduction, lane 0 writes segment mean.
    #pragma unroll
    for (int off = 16; off > 0; off >>= 1)
        sum += __shfl_down_sync(0xFFFFFFFFu, sum, off);
    if (lane == 0)
        out[gwarp] = sum * inv;
}

// Mid path: warp per segment, simple loop (L multiple of 128 floats).
__global__ __launch_bounds__(256) void seg_warp_kernel(
    const float* __restrict__ x,
    float* __restrict__ out,
    int n4, int nchunks, float inv, int num_segs)
{
    const int gwarp = (blockIdx.x * 256 + threadIdx.x) >> 5;
    const int lane  = threadIdx.x & 31;
    if (gwarp >= num_segs) return;

    const float4* __restrict__ p4 =
        reinterpret_cast<const float4*>(x) + (long long)gwarp * n4;

    float sum = 0.0f;
    float4 v = __ldg(p4 + lane);

    #pragma unroll 4
    for (int c = 1; c < nchunks; c++) {
        float4 nv = __ldg(p4 + c * 32 + lane);
        float src = (lane == 0) ? nv.x : v.x;
        float nx  = __shfl_sync(0xFFFFFFFFu, src, (lane + 1) & 31);
        sum += fabsf(v.y - v.x) + fabsf(v.z - v.y)
             + fabsf(v.w - v.z) + fabsf(nx  - v.w);
        v = nv;
    }
    {
        float nx = __shfl_sync(0xFFFFFFFFu, v.x, (lane + 1) & 31);
        if (lane == 31) nx = v.w;
        sum += fabsf(v.y - v.x) + fabsf(v.z - v.y)
             + fabsf(v.w - v.z) + fabsf(nx  - v.w);
    }

    #pragma unroll
    for (int off = 16; off > 0; off >>= 1)
        sum += __shfl_down_sync(0xFFFFFFFFu, sum, off);
    if (lane == 0)
        out[gwarp] = sum * inv;
}

// Generic fallback: one CTA per segment, scalar loads (any L >= 2).
__global__ __launch_bounds__(256) void seg_generic_kernel(
    const float* __restrict__ x,
    float* __restrict__ out,
    int L, float inv)
{
    const long long seg = blockIdx.x;
    const float* __restrict__ p = x + seg * (long long)L;
    const int tid = threadIdx.x;

    float sum = 0.0f;
    for (int i = tid; i < L - 1; i += blockDim.x)
        sum += fabsf(__ldg(p + i + 1) - __ldg(p + i));

    #pragma unroll
    for (int off = 16; off > 0; off >>= 1)
        sum += __shfl_down_sync(0xFFFFFFFFu, sum, off);

    __shared__ float wsum[8];
    const int lane = tid & 31, wid = tid >> 5;
    if (lane == 0) wsum[wid] = sum;
    __syncthreads();
    if (wid == 0) {
        float s = (lane < 8) ? wsum[lane] : 0.0f;
        #pragma unroll
        for (int off = 4; off > 0; off >>= 1)
            s += __shfl_down_sync(0xFFFFFFFFu, s, off);
        if (lane == 0) out[seg] = s * inv;
    }
}

extern "C" void kernel_launch(void* const* d_in, const int* in_sizes, int n_in,
                              void* d_out, int out_size)
{
    const float* x = (const float*)d_in[0];
    float* out = (float*)d_out;

    const long long total = (long long)in_sizes[0];
    const int num_segs = out_size;                     // B * target_len
    const int L = (int)(total / (long long)num_segs);  // segment length
    const float inv = 1.0f / (float)(L - 1);

    const int ctas = (num_segs * 32 + 255) / 256;

    if ((L % (BATCH * 128)) == 0 && L / (BATCH * 128) >= 2) {
        const int n4 = L >> 2;
        const int nbatches = n4 / (BATCH * 32);
        seg_warp_pipe_kernel<<<ctas, 256>>>(x, out, n4, nbatches, inv, num_segs);
    } else if ((L & 127) == 0) {
        const int n4 = L >> 2;
        seg_warp_kernel<<<ctas, 256>>>(x, out, n4, n4 >> 5, inv, num_segs);
    } else {
        seg_generic_kernel<<<num_segs, 256>>>(x, out, L, inv);
    }
}